// round 1
// baseline (speedup 1.0000x reference)
#include <cuda_runtime.h>

#define E     1024
#define LAY   24
#define HID   4096
#define VOCAB 50277
#define NBLK  148
#define NTHR  256
#define NWARP (NTHR / 32)
#define GWARPS (NBLK * NWARP)

// ---------------- scratch (device globals: no allocations allowed) ----------
__device__ float g_x[E];
__device__ float g_r[E];
__device__ float g_k[E];
__device__ float g_v[E];
__device__ float g_rf[E];
__device__ float g_kf[HID];
__device__ unsigned g_bar_count = 0;
__device__ volatile unsigned g_bar_gen = 0;

struct Params {
    const int*   ctx;
    const float *xx_att, *aa_att, *bb_att, *pp_att, *xx_ffn;
    const float *emb_w, *head_w;
    const float *ln0_w, *ln0_b, *ln1_w, *ln1_b, *ln2_w, *ln2_b, *lno_w, *lno_b;
    const float *mk, *mv, *mr, *tf, *td;
    const float *Wr, *Wk, *Wv, *Wo;
    const float *fmk, *fmr, *Fr, *Fk, *Fv;
    float* out;
};

// ---------------- software grid barrier (CG sync_grids pattern) -------------
__device__ __forceinline__ void grid_sync() {
    __syncthreads();
    if (threadIdx.x == 0) {
        unsigned gen = g_bar_gen;
        __threadfence();
        if (atomicAdd(&g_bar_count, 1u) == NBLK - 1u) {
            atomicExch(&g_bar_count, 0u);
            __threadfence();
            g_bar_gen = gen + 1u;
        } else {
            while (g_bar_gen == gen) { }
        }
        __threadfence();
    }
    __syncthreads();
}

// ---------------- block reduction (sum, broadcast) ---------------------------
__device__ __forceinline__ float block_sum(float v, float* red) {
    #pragma unroll
    for (int o = 16; o; o >>= 1) v += __shfl_xor_sync(0xffffffffu, v, o);
    int w = threadIdx.x >> 5;
    if ((threadIdx.x & 31) == 0) red[w] = v;
    __syncthreads();
    if (threadIdx.x < 32) {
        float t = (threadIdx.x < NWARP) ? red[threadIdx.x] : 0.f;
        #pragma unroll
        for (int o = 4; o; o >>= 1) t += __shfl_xor_sync(0xffffffffu, t, o);
        if (threadIdx.x == 0) red[0] = t;
    }
    __syncthreads();
    float r = red[0];
    __syncthreads();
    return r;
}

// two-pass LayerNorm: src (global) -> dst (shared), per-block redundant
__device__ void block_ln(const float* __restrict__ src,
                         const float* __restrict__ w,
                         const float* __restrict__ b,
                         float* dst, float* red) {
    float s = 0.f;
    for (int j = threadIdx.x; j < E; j += NTHR) { float t = src[j]; dst[j] = t; s += t; }
    float mean = block_sum(s, red) * (1.f / E);
    float s2 = 0.f;
    for (int j = threadIdx.x; j < E; j += NTHR) { float c = dst[j] - mean; s2 += c * c; }
    float inv = rsqrtf(block_sum(s2, red) * (1.f / E) + 1e-5f);
    for (int j = threadIdx.x; j < E; j += NTHR)
        dst[j] = (dst[j] - mean) * inv * w[j] + b[j];
    __syncthreads();
}

// warp-wide dot product: N4 float4 per lane (row length = N4*128 floats)
template <int N4>
__device__ __forceinline__ float warp_dot(const float4* __restrict__ W,
                                          const float4* __restrict__ v) {
    const int lane = threadIdx.x & 31;
    float s = 0.f;
    #pragma unroll
    for (int t = 0; t < N4; t++) {
        float4 a = W[lane + 32 * t];
        float4 x = v[lane + 32 * t];
        s = fmaf(a.x, x.x, s);
        s = fmaf(a.y, x.y, s);
        s = fmaf(a.z, x.z, s);
        s = fmaf(a.w, x.w, s);
    }
    #pragma unroll
    for (int o = 16; o; o >>= 1) s += __shfl_xor_sync(0xffffffffu, s, o);
    return s;
}

__device__ __forceinline__ float sigmoidf_(float x) {
    return 1.f / (1.f + expf(-x));
}

// ---------------- the whole network in one persistent kernel ----------------
__global__ void __launch_bounds__(NTHR, 1) rwkv_kernel(Params p) {
    __shared__ __align__(16) float sh[HID];   // 16KB, aliased per phase
    __shared__ float red[NWARP];

    const int tid  = threadIdx.x;
    const int gw   = blockIdx.x * NWARP + (tid >> 5);
    const int lane = tid & 31;

    float* outv  = p.out;                 // logits [V]
    float* o_xx  = p.out + VOCAB;         // xx_att_r [L,E]
    float* o_aa  = o_xx  + LAY * E;
    float* o_bb  = o_aa  + LAY * E;
    float* o_pp  = o_bb  + LAY * E;
    float* o_xxf = o_pp  + LAY * E;
    float* o_da  = o_xxf + LAY * E;       // r_pre
    float* o_db  = o_da  + LAY * E;       // sigmoid(r_pre)

    // ---- init: x0 = LN(emb[ctx], ln0) ----
    {
        int tok = p.ctx[0];
        block_ln(p.emb_w + (size_t)tok * E, p.ln0_w, p.ln0_b, sh, red);
        if (blockIdx.x == 0)
            for (int j = tid; j < E; j += NTHR) g_x[j] = sh[j];
    }
    grid_sync();

    for (int l = 0; l < LAY; l++) {
        const size_t lE  = (size_t)l * E;
        const size_t lEE = (size_t)l * E * E;

        // ================= Phase A: LN1 + mixes + r/k/v GEMVs ==============
        float* xn = sh; float* xk = sh + E; float* xv = sh + 2 * E; float* xr = sh + 3 * E;
        block_ln(g_x, p.ln1_w + lE, p.ln1_b + lE, xn, red);
        for (int j = tid; j < E; j += NTHR) {
            float xnj = xn[j], sx = p.xx_att[lE + j];
            float a = p.mk[lE + j], b = p.mv[lE + j], c = p.mr[lE + j];
            xk[j] = xnj * a + sx * (1.f - a);
            xv[j] = xnj * b + sx * (1.f - b);
            xr[j] = xnj * c + sx * (1.f - c);
            if (blockIdx.x == 0) o_xx[lE + j] = xnj;
        }
        __syncthreads();
        for (int row = gw; row < 3 * E; row += GWARPS) {
            int m = row >> 10;          // 0:r 1:k 2:v
            int i = row & (E - 1);
            const float* Wb  = (m == 0) ? p.Wr : (m == 1) ? p.Wk : p.Wv;
            const float* vec = (m == 0) ? xr   : (m == 1) ? xk   : xv;
            float s = warp_dot<8>((const float4*)(Wb + lEE + (size_t)i * E),
                                  (const float4*)vec);
            if (lane == 0) ((m == 0) ? g_r : (m == 1) ? g_k : g_v)[i] = s;
        }
        grid_sync();

        // ================= Phase B: WKV elementwise + Wo GEMV ==============
        float* oin = sh;
        for (int j = tid; j < E; j += NTHR) {
            float kj = g_k[j], vj = g_v[j], rp = g_r[j];
            float aa = p.aa_att[lE + j], bb = p.bb_att[lE + j], pp = p.pp_att[lE + j];
            float tf = p.tf[lE + j],     td = p.td[lE + j];
            float ww = tf + kj;
            float q  = fmaxf(pp, ww);
            float e1 = expf(pp - q), e2 = expf(ww - q);
            float a  = e1 * aa + e2 * vj;
            float b  = e1 * bb + e2;
            float rr = sigmoidf_(rp);
            oin[j] = rr * a / b;
            if (blockIdx.x == 0) {
                float ww2 = pp + td;
                float q2  = fmaxf(ww2, kj);
                float f1  = expf(ww2 - q2), f2 = expf(kj - q2);
                o_aa[lE + j] = f1 * aa + f2 * vj;
                o_bb[lE + j] = f1 * bb + f2;
                o_pp[lE + j] = q2;
                o_da[lE + j] = rp;
                o_db[lE + j] = rr;
            }
        }
        __syncthreads();
        for (int row = gw; row < E; row += GWARPS) {
            float s = warp_dot<8>((const float4*)(p.Wo + lEE + (size_t)row * E),
                                  (const float4*)oin);
            if (lane == 0) g_x[row] += s;
        }
        grid_sync();

        // ================= Phase C: LN2 + mixes + Fk/Fr GEMVs ==============
        float* xn2 = sh; float* fxk = sh + E; float* fxr = sh + 2 * E;
        block_ln(g_x, p.ln2_w + lE, p.ln2_b + lE, xn2, red);
        for (int j = tid; j < E; j += NTHR) {
            float v = xn2[j], sxf = p.xx_ffn[lE + j];
            float a = p.fmk[lE + j], b2 = p.fmr[lE + j];
            fxk[j] = v * a  + sxf * (1.f - a);
            fxr[j] = v * b2 + sxf * (1.f - b2);
            if (blockIdx.x == 0) o_xxf[lE + j] = v;
        }
        __syncthreads();
        const size_t lHE = (size_t)l * HID * E;
        for (int row = gw; row < HID + E; row += GWARPS) {
            if (row < HID) {
                float s = warp_dot<8>((const float4*)(p.Fk + lHE + (size_t)row * E),
                                      (const float4*)fxk);
                s = fmaxf(s, 0.f);
                if (lane == 0) g_kf[row] = s * s;
            } else {
                int i = row - HID;
                float s = warp_dot<8>((const float4*)(p.Fr + lEE + (size_t)i * E),
                                      (const float4*)fxr);
                if (lane == 0) g_rf[i] = sigmoidf_(s);
            }
        }
        grid_sync();

        // ================= Phase D: Fv GEMV + residual add =================
        for (int j = tid; j < HID; j += NTHR) sh[j] = g_kf[j];
        __syncthreads();
        const size_t lEH = (size_t)l * E * HID;
        for (int row = gw; row < E; row += GWARPS) {
            float s = warp_dot<32>((const float4*)(p.Fv + lEH + (size_t)row * HID),
                                   (const float4*)sh);
            if (lane == 0) g_x[row] += g_rf[row] * s;
        }
        grid_sync();
    }

    // ================= head: LN + [V,E] GEMV ===============================
    block_ln(g_x, p.lno_w, p.lno_b, sh, red);
    for (int row = gw; row < VOCAB; row += GWARPS) {
        float s = warp_dot<8>((const float4*)(p.head_w + (size_t)row * E),
                              (const float4*)sh);
        if (lane == 0) outv[row] = s;
    }
}

extern "C" void kernel_launch(void* const* d_in, const int* in_sizes, int n_in,
                              void* d_out, int out_size) {
    Params p;
    p.ctx    = (const int*)  d_in[0];
    p.xx_att = (const float*)d_in[1];
    p.aa_att = (const float*)d_in[2];
    p.bb_att = (const float*)d_in[3];
    p.pp_att = (const float*)d_in[4];
    p.xx_ffn = (const float*)d_in[5];
    p.emb_w  = (const float*)d_in[6];
    p.head_w = (const float*)d_in[7];
    p.ln0_w  = (const float*)d_in[8];
    p.ln0_b  = (const float*)d_in[9];
    p.ln1_w  = (const float*)d_in[10];
    p.ln1_b  = (const float*)d_in[11];
    p.ln2_w  = (const float*)d_in[12];
    p.ln2_b  = (const float*)d_in[13];
    p.lno_w  = (const float*)d_in[14];
    p.lno_b  = (const float*)d_in[15];
    p.mk     = (const float*)d_in[16];
    p.mv     = (const float*)d_in[17];
    p.mr     = (const float*)d_in[18];
    p.tf     = (const float*)d_in[19];
    p.td     = (const float*)d_in[20];
    p.Wr     = (const float*)d_in[21];
    p.Wk     = (const float*)d_in[22];
    p.Wv     = (const float*)d_in[23];
    p.Wo     = (const float*)d_in[24];
    p.fmk    = (const float*)d_in[25];
    p.fmr    = (const float*)d_in[26];
    p.Fr     = (const float*)d_in[27];
    p.Fk     = (const float*)d_in[28];
    p.Fv     = (const float*)d_in[29];
    p.out    = (float*)d_out;

    rwkv_kernel<<<NBLK, NTHR>>>(p);
}

// round 2
// speedup vs baseline: 1.0070x; 1.0070x over previous
#include <cuda_runtime.h>

#define E     1024
#define LAY   24
#define HID   4096
#define VOCAB 50277
#define NBLK  148
#define NTHR  512
#define NWARP (NTHR / 32)
#define GWARPS (NBLK * NWARP)

// ---------------- scratch (device globals: no allocations allowed) ----------
__device__ float g_x[E];
__device__ float g_r[E];
__device__ float g_k[E];
__device__ float g_v[E];
__device__ float g_rf[E];
__device__ float g_kf[HID];
__device__ unsigned g_bar_leaf[8] = {0,0,0,0,0,0,0,0};
__device__ unsigned g_bar_root = 0;
__device__ volatile unsigned g_bar_gen = 0;

struct Params {
    const int*   ctx;
    const float *xx_att, *aa_att, *bb_att, *pp_att, *xx_ffn;
    const float *emb_w, *head_w;
    const float *ln0_w, *ln0_b, *ln1_w, *ln1_b, *ln2_w, *ln2_b, *lno_w, *lno_b;
    const float *mk, *mv, *mr, *tf, *td;
    const float *Wr, *Wk, *Wv, *Wo;
    const float *fmk, *fmr, *Fr, *Fk, *Fv;
    float* out;
};

// ------------- two-level software grid barrier (8 leaf buckets + root) ------
__device__ __forceinline__ void grid_sync() {
    __syncthreads();
    if (threadIdx.x == 0) {
        const unsigned gen = g_bar_gen;
        const int b = blockIdx.x & 7;
        // 148 = 8*18+4 -> buckets 0..3 hold 19 blocks, 4..7 hold 18
        const unsigned cnt = 18u + (b < 4 ? 1u : 0u);
        __threadfence();
        if (atomicAdd(&g_bar_leaf[b], 1u) == cnt - 1u) {
            atomicExch(&g_bar_leaf[b], 0u);          // last in bucket resets it
            if (atomicAdd(&g_bar_root, 1u) == 7u) {  // last bucket releases
                atomicExch(&g_bar_root, 0u);
                __threadfence();
                g_bar_gen = gen + 1u;
            } else {
                while (g_bar_gen == gen) { }
            }
        } else {
            while (g_bar_gen == gen) { }
        }
        __threadfence();
    }
    __syncthreads();
}

// ---------------- block reduction (sum, broadcast) ---------------------------
__device__ __forceinline__ float block_sum(float v, float* red) {
    #pragma unroll
    for (int o = 16; o; o >>= 1) v += __shfl_xor_sync(0xffffffffu, v, o);
    int w = threadIdx.x >> 5;
    if ((threadIdx.x & 31) == 0) red[w] = v;
    __syncthreads();
    if (threadIdx.x < 32) {
        float t = (threadIdx.x < NWARP) ? red[threadIdx.x] : 0.f;
        #pragma unroll
        for (int o = 16; o; o >>= 1) t += __shfl_xor_sync(0xffffffffu, t, o);
        if (threadIdx.x == 0) red[0] = t;
    }
    __syncthreads();
    float r = red[0];
    __syncthreads();
    return r;
}

// two-pass LayerNorm: src (global) -> dst (shared), per-block redundant
__device__ void block_ln(const float* __restrict__ src,
                         const float* __restrict__ w,
                         const float* __restrict__ b,
                         float* dst, float* red) {
    float s = 0.f;
    for (int j = threadIdx.x; j < E; j += NTHR) { float t = src[j]; dst[j] = t; s += t; }
    float mean = block_sum(s, red) * (1.f / E);
    float s2 = 0.f;
    for (int j = threadIdx.x; j < E; j += NTHR) { float c = dst[j] - mean; s2 += c * c; }
    float inv = rsqrtf(block_sum(s2, red) * (1.f / E) + 1e-5f);
    for (int j = threadIdx.x; j < E; j += NTHR)
        dst[j] = (dst[j] - mean) * inv * w[j] + b[j];
    __syncthreads();
}

// warp dot, row length 1024: front-batched 8x LDG.128 (MLP=8), x from shared
__device__ __forceinline__ float warp_dot8(const float4* __restrict__ W,
                                           const float4* __restrict__ v,
                                           int lane) {
    float4 a[8];
    #pragma unroll
    for (int t = 0; t < 8; t++) a[t] = W[lane + 32 * t];
    float s = 0.f;
    #pragma unroll
    for (int t = 0; t < 8; t++) {
        float4 x = v[lane + 32 * t];
        s = fmaf(a[t].x, x.x, s);
        s = fmaf(a[t].y, x.y, s);
        s = fmaf(a[t].z, x.z, s);
        s = fmaf(a[t].w, x.w, s);
    }
    #pragma unroll
    for (int o = 16; o; o >>= 1) s += __shfl_xor_sync(0xffffffffu, s, o);
    return s;
}

// warp dot, row length 4096: 4 chunks of 8x LDG.128, 2-stage software pipeline
__device__ __forceinline__ float warp_dot32(const float4* __restrict__ W,
                                            const float4* __restrict__ v,
                                            int lane) {
    float4 a[8], b[8];
    #pragma unroll
    for (int t = 0; t < 8; t++) a[t] = W[lane + 32 * t];
    float s = 0.f;
    #pragma unroll
    for (int c = 0; c < 4; c++) {
        if (c < 3) {
            #pragma unroll
            for (int t = 0; t < 8; t++) b[t] = W[lane + 32 * t + 256 * (c + 1)];
        }
        #pragma unroll
        for (int t = 0; t < 8; t++) {
            float4 x = v[lane + 32 * t + 256 * c];
            s = fmaf(a[t].x, x.x, s);
            s = fmaf(a[t].y, x.y, s);
            s = fmaf(a[t].z, x.z, s);
            s = fmaf(a[t].w, x.w, s);
        }
        #pragma unroll
        for (int t = 0; t < 8; t++) a[t] = b[t];
    }
    #pragma unroll
    for (int o = 16; o; o >>= 1) s += __shfl_xor_sync(0xffffffffu, s, o);
    return s;
}

__device__ __forceinline__ float sigmoidf_(float x) {
    return 1.f / (1.f + expf(-x));
}

// ---------------- the whole network in one persistent kernel ----------------
__global__ void __launch_bounds__(NTHR, 1) rwkv_kernel(Params p) {
    __shared__ __align__(16) float sh[HID];   // 16KB, aliased per phase
    __shared__ float red[NWARP];

    const int tid  = threadIdx.x;
    const int gw   = blockIdx.x * NWARP + (tid >> 5);
    const int lane = tid & 31;

    float* outv  = p.out;                 // logits [V]
    float* o_xx  = p.out + VOCAB;         // xx_att_r [L,E]
    float* o_aa  = o_xx  + LAY * E;
    float* o_bb  = o_aa  + LAY * E;
    float* o_pp  = o_bb  + LAY * E;
    float* o_xxf = o_pp  + LAY * E;
    float* o_da  = o_xxf + LAY * E;       // r_pre
    float* o_db  = o_da  + LAY * E;       // sigmoid(r_pre)

    // ---- init: x0 = LN(emb[ctx], ln0) ----
    {
        int tok = p.ctx[0];
        block_ln(p.emb_w + (size_t)tok * E, p.ln0_w, p.ln0_b, sh, red);
        if (blockIdx.x == 0)
            for (int j = tid; j < E; j += NTHR) g_x[j] = sh[j];
    }
    grid_sync();

    for (int l = 0; l < LAY; l++) {
        const size_t lE  = (size_t)l * E;
        const size_t lEE = (size_t)l * E * E;

        // ================= Phase A: LN1 + mixes + r/k/v GEMVs ==============
        float* xn = sh; float* xk = sh + E; float* xv = sh + 2 * E; float* xr = sh + 3 * E;
        block_ln(g_x, p.ln1_w + lE, p.ln1_b + lE, xn, red);
        for (int j = tid; j < E; j += NTHR) {
            float xnj = xn[j], sx = p.xx_att[lE + j];
            float a = p.mk[lE + j], b = p.mv[lE + j], c = p.mr[lE + j];
            xk[j] = xnj * a + sx * (1.f - a);
            xv[j] = xnj * b + sx * (1.f - b);
            xr[j] = xnj * c + sx * (1.f - c);
            if (blockIdx.x == 0) o_xx[lE + j] = xnj;
        }
        __syncthreads();
        for (int row = gw; row < 3 * E; row += GWARPS) {
            int m = row >> 10;          // 0:r 1:k 2:v
            int i = row & (E - 1);
            const float* Wb  = (m == 0) ? p.Wr : (m == 1) ? p.Wk : p.Wv;
            const float* vec = (m == 0) ? xr   : (m == 1) ? xk   : xv;
            float s = warp_dot8((const float4*)(Wb + lEE + (size_t)i * E),
                                (const float4*)vec, lane);
            if (lane == 0) ((m == 0) ? g_r : (m == 1) ? g_k : g_v)[i] = s;
        }
        grid_sync();

        // ================= Phase B: WKV elementwise + Wo GEMV ==============
        float* oin = sh;
        for (int j = tid; j < E; j += NTHR) {
            float kj = g_k[j], vj = g_v[j], rp = g_r[j];
            float aa = p.aa_att[lE + j], bb = p.bb_att[lE + j], pp = p.pp_att[lE + j];
            float tf = p.tf[lE + j],     td = p.td[lE + j];
            float ww = tf + kj;
            float q  = fmaxf(pp, ww);
            float e1 = expf(pp - q), e2 = expf(ww - q);
            float a  = e1 * aa + e2 * vj;
            float b  = e1 * bb + e2;
            float rr = sigmoidf_(rp);
            oin[j] = rr * a / b;
            if (blockIdx.x == 0) {
                float ww2 = pp + td;
                float q2  = fmaxf(ww2, kj);
                float f1  = expf(ww2 - q2), f2 = expf(kj - q2);
                o_aa[lE + j] = f1 * aa + f2 * vj;
                o_bb[lE + j] = f1 * bb + f2;
                o_pp[lE + j] = q2;
                o_da[lE + j] = rp;
                o_db[lE + j] = rr;
            }
        }
        __syncthreads();
        for (int row = gw; row < E; row += GWARPS) {
            float s = warp_dot8((const float4*)(p.Wo + lEE + (size_t)row * E),
                                (const float4*)oin, lane);
            if (lane == 0) g_x[row] += s;
        }
        grid_sync();

        // ================= Phase C: LN2 + mixes + Fk/Fr GEMVs ==============
        float* xn2 = sh; float* fxk = sh + E; float* fxr = sh + 2 * E;
        block_ln(g_x, p.ln2_w + lE, p.ln2_b + lE, xn2, red);
        for (int j = tid; j < E; j += NTHR) {
            float v = xn2[j], sxf = p.xx_ffn[lE + j];
            float a = p.fmk[lE + j], b2 = p.fmr[lE + j];
            fxk[j] = v * a  + sxf * (1.f - a);
            fxr[j] = v * b2 + sxf * (1.f - b2);
            if (blockIdx.x == 0) o_xxf[lE + j] = v;
        }
        __syncthreads();
        const size_t lHE = (size_t)l * HID * E;
        for (int row = gw; row < HID + E; row += GWARPS) {
            if (row < HID) {
                float s = warp_dot8((const float4*)(p.Fk + lHE + (size_t)row * E),
                                    (const float4*)fxk, lane);
                s = fmaxf(s, 0.f);
                if (lane == 0) g_kf[row] = s * s;
            } else {
                int i = row - HID;
                float s = warp_dot8((const float4*)(p.Fr + lEE + (size_t)i * E),
                                    (const float4*)fxr, lane);
                if (lane == 0) g_rf[i] = sigmoidf_(s);
            }
        }
        grid_sync();

        // ================= Phase D: Fv GEMV + residual add =================
        for (int j = tid; j < HID; j += NTHR) sh[j] = g_kf[j];
        __syncthreads();
        const size_t lEH = (size_t)l * E * HID;
        for (int row = gw; row < E; row += GWARPS) {
            float s = warp_dot32((const float4*)(p.Fv + lEH + (size_t)row * HID),
                                 (const float4*)sh, lane);
            if (lane == 0) g_x[row] += g_rf[row] * s;
        }
        grid_sync();
    }

    // ================= head: LN + [V,E] GEMV ===============================
    block_ln(g_x, p.lno_w, p.lno_b, sh, red);
    for (int row = gw; row < VOCAB; row += GWARPS) {
        float s = warp_dot8((const float4*)(p.head_w + (size_t)row * E),
                            (const float4*)sh, lane);
        if (lane == 0) outv[row] = s;
    }
}

extern "C" void kernel_launch(void* const* d_in, const int* in_sizes, int n_in,
                              void* d_out, int out_size) {
    Params p;
    p.ctx    = (const int*)  d_in[0];
    p.xx_att = (const float*)d_in[1];
    p.aa_att = (const float*)d_in[2];
    p.bb_att = (const float*)d_in[3];
    p.pp_att = (const float*)d_in[4];
    p.xx_ffn = (const float*)d_in[5];
    p.emb_w  = (const float*)d_in[6];
    p.head_w = (const float*)d_in[7];
    p.ln0_w  = (const float*)d_in[8];
    p.ln0_b  = (const float*)d_in[9];
    p.ln1_w  = (const float*)d_in[10];
    p.ln1_b  = (const float*)d_in[11];
    p.ln2_w  = (const float*)d_in[12];
    p.ln2_b  = (const float*)d_in[13];
    p.lno_w  = (const float*)d_in[14];
    p.lno_b  = (const float*)d_in[15];
    p.mk     = (const float*)d_in[16];
    p.mv     = (const float*)d_in[17];
    p.mr     = (const float*)d_in[18];
    p.tf     = (const float*)d_in[19];
    p.td     = (const float*)d_in[20];
    p.Wr     = (const float*)d_in[21];
    p.Wk     = (const float*)d_in[22];
    p.Wv     = (const float*)d_in[23];
    p.Wo     = (const float*)d_in[24];
    p.fmk    = (const float*)d_in[25];
    p.fmr    = (const float*)d_in[26];
    p.Fr     = (const float*)d_in[27];
    p.Fk     = (const float*)d_in[28];
    p.Fv     = (const float*)d_in[29];
    p.out    = (float*)d_out;

    rwkv_kernel<<<NBLK, NTHR>>>(p);
}

// round 3
// speedup vs baseline: 1.3442x; 1.3349x over previous
#include <cuda_runtime.h>

#define E     1024
#define LAY   24
#define HID   4096
#define VOCAB 50277
#define NBLK  148
#define NTHR  512
#define NWARP (NTHR / 32)
#define GWARPS (NBLK * NWARP)   // 2368

// ---------------- scratch (device globals: no allocations allowed) ----------
__device__ float g_x[E];
__device__ float g_r[E];
__device__ float g_k[E];
__device__ float g_v[E];
__device__ float g_rf[E];
__device__ float g_kf[HID];
__device__ unsigned g_bar_leaf[8] = {0,0,0,0,0,0,0,0};
__device__ unsigned g_bar_root = 0;
__device__ volatile unsigned g_bar_gen = 0;

struct Params {
    const int*   ctx;
    const float *xx_att, *aa_att, *bb_att, *pp_att, *xx_ffn;
    const float *emb_w, *head_w;
    const float *ln0_w, *ln0_b, *ln1_w, *ln1_b, *ln2_w, *ln2_b, *lno_w, *lno_b;
    const float *mk, *mv, *mr, *tf, *td;
    const float *Wr, *Wk, *Wv, *Wo;
    const float *fmk, *fmr, *Fr, *Fk, *Fv;
    float* out;
};

// ------------- two-level software grid barrier (8 leaf buckets + root) ------
__device__ __forceinline__ void grid_sync() {
    __syncthreads();
    if (threadIdx.x == 0) {
        const unsigned gen = g_bar_gen;
        const int b = blockIdx.x & 7;
        const unsigned cnt = 18u + (b < 4 ? 1u : 0u);   // 148 = 4*19 + 4*18
        __threadfence();
        if (atomicAdd(&g_bar_leaf[b], 1u) == cnt - 1u) {
            atomicExch(&g_bar_leaf[b], 0u);
            if (atomicAdd(&g_bar_root, 1u) == 7u) {
                atomicExch(&g_bar_root, 0u);
                __threadfence();
                g_bar_gen = gen + 1u;
            } else {
                while (g_bar_gen == gen) { __nanosleep(32); }
            }
        } else {
            while (g_bar_gen == gen) { __nanosleep(32); }
        }
        __threadfence();
    }
    __syncthreads();
}

// ---------------- block reduction (sum, broadcast) ---------------------------
__device__ __forceinline__ float block_sum(float v, float* red) {
    #pragma unroll
    for (int o = 16; o; o >>= 1) v += __shfl_xor_sync(0xffffffffu, v, o);
    int w = threadIdx.x >> 5;
    if ((threadIdx.x & 31) == 0) red[w] = v;
    __syncthreads();
    if (threadIdx.x < 32) {
        float t = (threadIdx.x < NWARP) ? red[threadIdx.x] : 0.f;
        #pragma unroll
        for (int o = 16; o; o >>= 1) t += __shfl_xor_sync(0xffffffffu, t, o);
        if (threadIdx.x == 0) red[0] = t;
    }
    __syncthreads();
    float r = red[0];
    __syncthreads();
    return r;
}

// two-pass LayerNorm: src (global) -> dst (shared), per-block redundant
__device__ void block_ln(const float* __restrict__ src,
                         const float* __restrict__ w,
                         const float* __restrict__ b,
                         float* dst, float* red) {
    float s = 0.f;
    for (int j = threadIdx.x; j < E; j += NTHR) { float t = src[j]; dst[j] = t; s += t; }
    float mean = block_sum(s, red) * (1.f / E);
    float s2 = 0.f;
    for (int j = threadIdx.x; j < E; j += NTHR) { float c = dst[j] - mean; s2 += c * c; }
    float inv = rsqrtf(block_sum(s2, red) * (1.f / E) + 1e-5f);
    for (int j = threadIdx.x; j < E; j += NTHR)
        dst[j] = (dst[j] - mean) * inv * w[j] + b[j];
    __syncthreads();
}

// ---------------- GEMV pieces ------------------------------------------------
__device__ __forceinline__ float red32(float s) {
    #pragma unroll
    for (int o = 16; o; o >>= 1) s += __shfl_xor_sync(0xffffffffu, s, o);
    return s;
}

// issue 8 LDG.128 of one 1024-float row into registers (prefetch)
__device__ __forceinline__ void pf8(const float* __restrict__ Wrow, int lane,
                                    float4 (&a)[8]) {
    const float4* W = (const float4*)Wrow;
    #pragma unroll
    for (int t = 0; t < 8; t++) a[t] = W[lane + 32 * t];
}

// consume prefetched row against a shared vector
__device__ __forceinline__ float dot8_pf(const float4 (&a)[8],
                                         const float* __restrict__ vec, int lane) {
    const float4* v = (const float4*)vec;
    float s = 0.f;
    #pragma unroll
    for (int t = 0; t < 8; t++) {
        float4 x = v[lane + 32 * t];
        s = fmaf(a[t].x, x.x, s);
        s = fmaf(a[t].y, x.y, s);
        s = fmaf(a[t].z, x.z, s);
        s = fmaf(a[t].w, x.w, s);
    }
    return red32(s);
}

__device__ __forceinline__ float warp_dot8(const float* __restrict__ Wrow,
                                           const float* __restrict__ vec, int lane) {
    float4 a[8];
    pf8(Wrow, lane, a);
    return dot8_pf(a, vec, lane);
}

// 4096-long row: chunk0 prefetched in a[], chunks 1..3 double-buffered
__device__ __forceinline__ float dot32_pf(float4 (&a)[8],
                                          const float* __restrict__ Wrow,
                                          const float* __restrict__ vec, int lane) {
    const float4* W = (const float4*)Wrow;
    const float4* v = (const float4*)vec;
    float4 b[8];
    float s = 0.f;
    #pragma unroll
    for (int c = 0; c < 4; c++) {
        if (c < 3) {
            #pragma unroll
            for (int t = 0; t < 8; t++) b[t] = W[lane + 32 * t + 256 * (c + 1)];
        }
        #pragma unroll
        for (int t = 0; t < 8; t++) {
            float4 x = v[lane + 32 * t + 256 * c];
            s = fmaf(a[t].x, x.x, s);
            s = fmaf(a[t].y, x.y, s);
            s = fmaf(a[t].z, x.z, s);
            s = fmaf(a[t].w, x.w, s);
        }
        #pragma unroll
        for (int t = 0; t < 8; t++) a[t] = b[t];
    }
    return red32(s);
}

__device__ __forceinline__ float sigmoidf_(float x) {
    return 1.f / (1.f + expf(-x));
}

// ---------------- the whole network in one persistent kernel ----------------
__global__ void __launch_bounds__(NTHR, 1) rwkv_kernel(Params p) {
    __shared__ __align__(16) float sh[HID];   // 16KB, aliased per phase
    __shared__ float red[NWARP];

    const int tid  = threadIdx.x;
    const int gw   = blockIdx.x * NWARP + (tid >> 5);
    const int lane = tid & 31;

    float* outv  = p.out;                 // logits [V]
    float* o_xx  = p.out + VOCAB;         // xx_att_r [L,E]
    float* o_aa  = o_xx  + LAY * E;
    float* o_bb  = o_aa  + LAY * E;
    float* o_pp  = o_bb  + LAY * E;
    float* o_xxf = o_pp  + LAY * E;
    float* o_da  = o_xxf + LAY * E;       // r_pre
    float* o_db  = o_da  + LAY * E;       // sigmoid(r_pre)

    float4 a[8];                          // cross-barrier prefetch buffer

    // ---- init: x0 = LN(emb[ctx], ln0) ----
    {
        int tok = p.ctx[0];
        block_ln(p.emb_w + (size_t)tok * E, p.ln0_w, p.ln0_b, sh, red);
        if (blockIdx.x == 0)
            for (int j = tid; j < E; j += NTHR) g_x[j] = sh[j];
    }
    // prefetch phase-A (layer 0) row gw before the first barrier
    {
        int m = gw >> 10, i = gw & (E - 1);
        const float* Wb = (m == 0) ? p.Wr : (m == 1) ? p.Wk : p.Wv;
        pf8(Wb + (size_t)i * E, lane, a);
    }
    grid_sync();

    for (int l = 0; l < LAY; l++) {
        const size_t lE  = (size_t)l * E;
        const size_t lEE = (size_t)l * E * E;

        // ================= Phase A: LN1 + mixes + r/k/v GEMVs ==============
        float* xn = sh; float* xk = sh + E; float* xv = sh + 2 * E; float* xr = sh + 3 * E;
        block_ln(g_x, p.ln1_w + lE, p.ln1_b + lE, xn, red);
        for (int j = tid; j < E; j += NTHR) {
            float xnj = xn[j], sx = p.xx_att[lE + j];
            float ak = p.mk[lE + j], bv = p.mv[lE + j], cr = p.mr[lE + j];
            xk[j] = xnj * ak + sx * (1.f - ak);
            xv[j] = xnj * bv + sx * (1.f - bv);
            xr[j] = xnj * cr + sx * (1.f - cr);
            if (blockIdx.x == 0) o_xx[lE + j] = xnj;
        }
        __syncthreads();
        {
            int m = gw >> 10, i = gw & (E - 1);
            const float* vec = (m == 0) ? xr : (m == 1) ? xk : xv;
            float s = dot8_pf(a, vec, lane);
            if (lane == 0) ((m == 0) ? g_r : (m == 1) ? g_k : g_v)[i] = s;
        }
        for (int row = gw + GWARPS; row < 3 * E; row += GWARPS) {
            int m = row >> 10, i = row & (E - 1);
            const float* Wb  = (m == 0) ? p.Wr : (m == 1) ? p.Wk : p.Wv;
            const float* vec = (m == 0) ? xr   : (m == 1) ? xk   : xv;
            float s = warp_dot8(Wb + lEE + (size_t)i * E, vec, lane);
            if (lane == 0) ((m == 0) ? g_r : (m == 1) ? g_k : g_v)[i] = s;
        }
        // prefetch phase-B (Wo) row
        if (gw < E) pf8(p.Wo + lEE + (size_t)gw * E, lane, a);
        grid_sync();

        // ================= Phase B: WKV elementwise + Wo GEMV ==============
        float* oin = sh;
        for (int j = tid; j < E; j += NTHR) {
            float kj = g_k[j], vj = g_v[j], rp = g_r[j];
            float aa = p.aa_att[lE + j], bb = p.bb_att[lE + j], pp = p.pp_att[lE + j];
            float tf = p.tf[lE + j],     td = p.td[lE + j];
            float ww = tf + kj;
            float q  = fmaxf(pp, ww);
            float e1 = expf(pp - q), e2 = expf(ww - q);
            float av = e1 * aa + e2 * vj;
            float bv = e1 * bb + e2;
            float rr = sigmoidf_(rp);
            oin[j] = rr * av / bv;
            if (blockIdx.x == 0) {
                float ww2 = pp + td;
                float q2  = fmaxf(ww2, kj);
                float f1  = expf(ww2 - q2), f2 = expf(kj - q2);
                o_aa[lE + j] = f1 * aa + f2 * vj;
                o_bb[lE + j] = f1 * bb + f2;
                o_pp[lE + j] = q2;
                o_da[lE + j] = rp;
                o_db[lE + j] = rr;
            }
        }
        __syncthreads();
        if (gw < E) {
            float s = dot8_pf(a, oin, lane);
            if (lane == 0) g_x[gw] += s;
        }
        // prefetch phase-C row (gw < 2368 < HID so always an Fk row)
        pf8(p.Fk + (size_t)l * HID * E + (size_t)gw * E, lane, a);
        grid_sync();

        // ================= Phase C: LN2 + mixes + Fk/Fr GEMVs ==============
        float* xn2 = sh; float* fxk = sh + E; float* fxr = sh + 2 * E;
        block_ln(g_x, p.ln2_w + lE, p.ln2_b + lE, xn2, red);
        for (int j = tid; j < E; j += NTHR) {
            float v = xn2[j], sxf = p.xx_ffn[lE + j];
            float ak = p.fmk[lE + j], br = p.fmr[lE + j];
            fxk[j] = v * ak + sxf * (1.f - ak);
            fxr[j] = v * br + sxf * (1.f - br);
            if (blockIdx.x == 0) o_xxf[lE + j] = v;
        }
        __syncthreads();
        {
            float s = dot8_pf(a, fxk, lane);
            s = fmaxf(s, 0.f);
            if (lane == 0) g_kf[gw] = s * s;
        }
        const size_t lHE = (size_t)l * HID * E;
        for (int row = gw + GWARPS; row < HID + E; row += GWARPS) {
            if (row < HID) {
                float s = warp_dot8(p.Fk + lHE + (size_t)row * E, fxk, lane);
                s = fmaxf(s, 0.f);
                if (lane == 0) g_kf[row] = s * s;
            } else {
                int i = row - HID;
                float s = warp_dot8(p.Fr + lEE + (size_t)i * E, fxr, lane);
                if (lane == 0) g_rf[i] = sigmoidf_(s);
            }
        }
        // prefetch phase-D (Fv) first chunk
        const size_t lEH = (size_t)l * E * HID;
        if (gw < E) pf8(p.Fv + lEH + (size_t)gw * HID, lane, a);
        grid_sync();

        // ================= Phase D: Fv GEMV + residual add =================
        for (int j = tid; j < HID; j += NTHR) sh[j] = g_kf[j];
        __syncthreads();
        if (gw < E) {
            float s = dot32_pf(a, p.Fv + lEH + (size_t)gw * HID, sh, lane);
            if (lane == 0) g_x[gw] += g_rf[gw] * s;
        }
        // prefetch next phase-A row (layer l+1), or head row after last layer
        if (l + 1 < LAY) {
            int m = gw >> 10, i = gw & (E - 1);
            const float* Wb = (m == 0) ? p.Wr : (m == 1) ? p.Wk : p.Wv;
            pf8(Wb + (size_t)(l + 1) * E * E + (size_t)i * E, lane, a);
        } else {
            pf8(p.head_w + (size_t)gw * E, lane, a);
        }
        grid_sync();
    }

    // ================= head: LN + [V,E] GEMV ===============================
    block_ln(g_x, p.lno_w, p.lno_b, sh, red);
    {
        float s = dot8_pf(a, sh, lane);
        if (lane == 0) outv[gw] = s;
    }
    int row = gw + GWARPS;
    for (; row + GWARPS < VOCAB; row += 2 * GWARPS) {
        float4 a0[8], a1[8];
        pf8(p.head_w + (size_t)row * E, lane, a0);
        pf8(p.head_w + (size_t)(row + GWARPS) * E, lane, a1);
        float s0 = dot8_pf(a0, sh, lane);
        float s1 = dot8_pf(a1, sh, lane);
        if (lane == 0) { outv[row] = s0; outv[row + GWARPS] = s1; }
    }
    for (; row < VOCAB; row += GWARPS) {
        float s = warp_dot8(p.head_w + (size_t)row * E, sh, lane);
        if (lane == 0) outv[row] = s;
    }
}

extern "C" void kernel_launch(void* const* d_in, const int* in_sizes, int n_in,
                              void* d_out, int out_size) {
    Params p;
    p.ctx    = (const int*)  d_in[0];
    p.xx_att = (const float*)d_in[1];
    p.aa_att = (const float*)d_in[2];
    p.bb_att = (const float*)d_in[3];
    p.pp_att = (const float*)d_in[4];
    p.xx_ffn = (const float*)d_in[5];
    p.emb_w  = (const float*)d_in[6];
    p.head_w = (const float*)d_in[7];
    p.ln0_w  = (const float*)d_in[8];
    p.ln0_b  = (const float*)d_in[9];
    p.ln1_w  = (const float*)d_in[10];
    p.ln1_b  = (const float*)d_in[11];
    p.ln2_w  = (const float*)d_in[12];
    p.ln2_b  = (const float*)d_in[13];
    p.lno_w  = (const float*)d_in[14];
    p.lno_b  = (const float*)d_in[15];
    p.mk     = (const float*)d_in[16];
    p.mv     = (const float*)d_in[17];
    p.mr     = (const float*)d_in[18];
    p.tf     = (const float*)d_in[19];
    p.td     = (const float*)d_in[20];
    p.Wr     = (const float*)d_in[21];
    p.Wk     = (const float*)d_in[22];
    p.Wv     = (const float*)d_in[23];
    p.Wo     = (const float*)d_in[24];
    p.fmk    = (const float*)d_in[25];
    p.fmr    = (const float*)d_in[26];
    p.Fr     = (const float*)d_in[27];
    p.Fk     = (const float*)d_in[28];
    p.Fv     = (const float*)d_in[29];
    p.out    = (float*)d_out;

    rwkv_kernel<<<NBLK, NTHR>>>(p);
}